// round 1
// baseline (speedup 1.0000x reference)
#include <cuda_runtime.h>
#include <math.h>

// Problem shape (fixed for this dataset entry)
#define Bn 4
#define Ln 8192
#define Dn 1024
#define BLn (Bn * Ln)   // 32768 tokens

// ---------------------------------------------------------------------------
// Scratch (device globals: allocation-free per harness rules)
// ---------------------------------------------------------------------------
__device__ float  g_q[(size_t)BLn * Dn];   // 128 MB
__device__ float  g_k[(size_t)BLn * Dn];   // 128 MB
__device__ int    g_src[BLn];              // source token index per compressed slot
__device__ int    g_len[Bn];
__device__ double g_sumP[Bn];

// ---------------------------------------------------------------------------
// SGEMM: C[m,n] = sum_k X[m,k] * W[n,k]   (X: 32768x1024, W: 1024x1024)
// 128x128 tile, BK=8, 256 threads, 8x8 per-thread microtile, double-buffered.
// blockIdx.z selects (Wq -> g_q) vs (Wk -> g_k).
// ---------------------------------------------------------------------------
__global__ __launch_bounds__(256, 2)
void sgemm_qk(const float* __restrict__ X,
              const float* __restrict__ Wq,
              const float* __restrict__ Wk)
{
    __shared__ float As[2][8][128];
    __shared__ float Bs[2][8][128];

    const float* W = (blockIdx.z == 0) ? Wq : Wk;
    float*       C = (blockIdx.z == 0) ? g_q : g_k;

    const int tid = threadIdx.x;
    const int sr  = tid >> 1;          // 0..127 : tile row loaded by this thread
    const int kc  = (tid & 1) << 2;    // 0 or 4 : k-subcolumn (float4)

    const float* aptr = X + ((size_t)blockIdx.y * 128 + sr) * Dn + kc;
    const float* bptr = W + ((size_t)blockIdx.x * 128 + sr) * Dn + kc;

    const int ty = tid >> 4;           // 0..15
    const int tx = tid & 15;           // 0..15

    float acc[8][8];
    #pragma unroll
    for (int i = 0; i < 8; i++) {
        #pragma unroll
        for (int j = 0; j < 8; j++) acc[i][j] = 0.0f;
    }

    float4 a4 = *(const float4*)aptr;
    float4 b4 = *(const float4*)bptr;
    As[0][kc + 0][sr] = a4.x; As[0][kc + 1][sr] = a4.y;
    As[0][kc + 2][sr] = a4.z; As[0][kc + 3][sr] = a4.w;
    Bs[0][kc + 0][sr] = b4.x; Bs[0][kc + 1][sr] = b4.y;
    Bs[0][kc + 2][sr] = b4.z; Bs[0][kc + 3][sr] = b4.w;
    __syncthreads();

    int buf = 0;
    #pragma unroll 1
    for (int kt = 0; kt < Dn / 8; kt++) {
        if (kt < Dn / 8 - 1) {
            a4 = *(const float4*)(aptr + (size_t)(kt + 1) * 8);
            b4 = *(const float4*)(bptr + (size_t)(kt + 1) * 8);
        }
        #pragma unroll
        for (int kk = 0; kk < 8; kk++) {
            float ar[8], br[8];
            *(float4*)&ar[0] = *(const float4*)&As[buf][kk][ty * 8];
            *(float4*)&ar[4] = *(const float4*)&As[buf][kk][ty * 8 + 4];
            *(float4*)&br[0] = *(const float4*)&Bs[buf][kk][tx * 8];
            *(float4*)&br[4] = *(const float4*)&Bs[buf][kk][tx * 8 + 4];
            #pragma unroll
            for (int i = 0; i < 8; i++) {
                #pragma unroll
                for (int j = 0; j < 8; j++)
                    acc[i][j] = fmaf(ar[i], br[j], acc[i][j]);
            }
        }
        if (kt < Dn / 8 - 1) {
            const int nb = buf ^ 1;
            As[nb][kc + 0][sr] = a4.x; As[nb][kc + 1][sr] = a4.y;
            As[nb][kc + 2][sr] = a4.z; As[nb][kc + 3][sr] = a4.w;
            Bs[nb][kc + 0][sr] = b4.x; Bs[nb][kc + 1][sr] = b4.y;
            Bs[nb][kc + 2][sr] = b4.z; Bs[nb][kc + 3][sr] = b4.w;
            __syncthreads();
            buf = nb;
        }
    }

    const size_t row0 = (size_t)blockIdx.y * 128 + ty * 8;
    const int    col0 = blockIdx.x * 128 + tx * 8;
    #pragma unroll
    for (int i = 0; i < 8; i++) {
        *(float4*)&C[(row0 + i) * Dn + col0] =
            make_float4(acc[i][0], acc[i][1], acc[i][2], acc[i][3]);
        *(float4*)&C[(row0 + i) * Dn + col0 + 4] =
            make_float4(acc[i][4], acc[i][5], acc[i][6], acc[i][7]);
    }
}

// ---------------------------------------------------------------------------
// Per-token: ||q_l||, ||k_{l-1}||, q_l . k_{l-1}  ->  p, b  (fp64 reductions)
// One block (128 threads) per token.
// ---------------------------------------------------------------------------
__global__ void props_kernel(float* __restrict__ out_p, float* __restrict__ out_b)
{
    const int t   = blockIdx.x;
    const int l   = t & (Ln - 1);
    const int tid = threadIdx.x;

    if (l == 0) {
        if (tid == 0) { out_p[t] = 1.0f; out_b[t] = 1.0f; }
        return;
    }

    const float4* qr = (const float4*)(g_q + (size_t)t * Dn);
    const float4* kr = (const float4*)(g_k + (size_t)(t - 1) * Dn);

    double sq = 0.0, sk = 0.0, sp = 0.0;
    #pragma unroll
    for (int it = 0; it < 2; it++) {
        const float4 qv = qr[tid + it * 128];
        const float4 kv = kr[tid + it * 128];
        sq += (double)qv.x * qv.x + (double)qv.y * qv.y +
              (double)qv.z * qv.z + (double)qv.w * qv.w;
        sk += (double)kv.x * kv.x + (double)kv.y * kv.y +
              (double)kv.z * kv.z + (double)kv.w * kv.w;
        sp += (double)qv.x * kv.x + (double)qv.y * kv.y +
              (double)qv.z * kv.z + (double)qv.w * kv.w;
    }
    #pragma unroll
    for (int o = 16; o > 0; o >>= 1) {
        sq += __shfl_down_sync(0xffffffffu, sq, o);
        sk += __shfl_down_sync(0xffffffffu, sk, o);
        sp += __shfl_down_sync(0xffffffffu, sp, o);
    }
    __shared__ double sh[3][4];
    const int wid = tid >> 5, lane = tid & 31;
    if (lane == 0) { sh[0][wid] = sq; sh[1][wid] = sk; sh[2][wid] = sp; }
    __syncthreads();
    if (tid == 0) {
        const double SQ = sh[0][0] + sh[0][1] + sh[0][2] + sh[0][3];
        const double SK = sh[1][0] + sh[1][1] + sh[1][2] + sh[1][3];
        const double SP = sh[2][0] + sh[2][1] + sh[2][2] + sh[2][3];
        const float nq = fmaxf(sqrtf((float)SQ), 1e-12f);
        const float nk = fmaxf(sqrtf((float)SK), 1e-12f);
        const float cs = (float)SP / (nq * nk);
        const float pv = 0.5f * (1.0f - cs);
        out_p[t] = pv;
        out_b[t] = (pv >= 0.5f) ? 1.0f : 0.0f;
    }
}

// ---------------------------------------------------------------------------
// Per-batch scan of b: compressed slots, P_down, lengths, sum(p).
// One block (256 threads) per batch; each thread owns 32 consecutive tokens.
// ---------------------------------------------------------------------------
__global__ void scan_kernel(const float* __restrict__ p_arr,
                            const float* __restrict__ b_arr,
                            float* __restrict__ P_down,
                            float* __restrict__ out_len)
{
    const int batch = blockIdx.x;
    const int tid   = threadIdx.x;          // 256
    const float* bb = b_arr + batch * Ln;
    const float* pp = p_arr + batch * Ln;
    const int base  = tid * 32;

    int    cnt  = 0;
    double sump = 0.0;
    #pragma unroll 8
    for (int j = 0; j < 32; j++) {
        const float bv = bb[base + j];
        cnt  += (bv > 0.5f) ? 1 : 0;
        sump += (double)pp[base + j];
    }

    const int lane = tid & 31, wid = tid >> 5;
    int v = cnt;
    #pragma unroll
    for (int o = 1; o < 32; o <<= 1) {
        const int n = __shfl_up_sync(0xffffffffu, v, o);
        if (lane >= o) v += n;
    }
    __shared__ int wsum[8], woff[8], stotal;
    if (lane == 31) wsum[wid] = v;
    __syncthreads();
    if (tid == 0) {
        int s = 0;
        for (int w = 0; w < 8; w++) { woff[w] = s; s += wsum[w]; }
        stotal = s;
    }
    __syncthreads();

    int slot = woff[wid] + v - cnt;          // exclusive prefix
    const int total = stotal;

    for (int j = 0; j < 32; j++) {
        const float bv = bb[base + j];
        if (bv > 0.5f) {
            const int l = base + j;
            g_src[batch * Ln + slot]  = l;
            P_down[batch * Ln + slot] = pp[l];
            slot++;
        }
    }
    for (int s = total + tid; s < Ln; s += 256)
        P_down[batch * Ln + s] = 0.0f;

    #pragma unroll
    for (int o = 16; o > 0; o >>= 1)
        sump += __shfl_down_sync(0xffffffffu, sump, o);
    __shared__ double psh[8];
    if (lane == 0) psh[wid] = sump;
    __syncthreads();
    if (tid == 0) {
        double s = 0.0;
        for (int w = 0; w < 8; w++) s += psh[w];
        g_sumP[batch]   = s;
        g_len[batch]    = total;
        out_len[batch]  = (float)total;
    }
}

// ---------------------------------------------------------------------------
// Gather: x_down[i, j] = (j < len_i) ? x[i, src] : 0.   One block per row.
// ---------------------------------------------------------------------------
__global__ void gather_kernel(const float* __restrict__ x, float* __restrict__ x_down)
{
    const int row   = blockIdx.x;            // 0..32767
    const int batch = row >> 13;
    const int j     = row & (Ln - 1);
    const int tid   = threadIdx.x;            // 256, 1 float4 each

    float4* dst = (float4*)(x_down + (size_t)row * Dn);
    if (j < g_len[batch]) {
        const int src = g_src[row];
        const float4* s = (const float4*)(x + (size_t)(batch * Ln + src) * Dn);
        dst[tid] = s[tid];
    } else {
        dst[tid] = make_float4(0.f, 0.f, 0.f, 0.f);
    }
}

// ---------------------------------------------------------------------------
// ratio_loss = N/(N-1) * ((N-1)*F*G + (1-F)*(1-G)),  N = 6
// ---------------------------------------------------------------------------
__global__ void finalize_kernel(float* __restrict__ o_loss)
{
    double sb = 0.0, sp = 0.0;
    for (int i = 0; i < Bn; i++) { sb += (double)g_len[i]; sp += g_sumP[i]; }
    const double F = sb / (double)BLn;
    const double G = sp / (double)BLn;
    const double N = 6.0;
    o_loss[0] = (float)(N / (N - 1.0) * ((N - 1.0) * F * G + (1.0 - F) * (1.0 - G)));
}

// ---------------------------------------------------------------------------
// Launch. Output layout (f32): x_down | P_down | b | p | lengths | ratio_loss
// ---------------------------------------------------------------------------
extern "C" void kernel_launch(void* const* d_in, const int* in_sizes, int n_in,
                              void* d_out, int out_size)
{
    const float* x  = (const float*)d_in[0];
    const float* Wq = (const float*)d_in[1];
    const float* Wk = (const float*)d_in[2];

    float* out    = (float*)d_out;
    float* o_xd   = out;
    float* o_P    = out + (size_t)BLn * Dn;
    float* o_b    = o_P + BLn;
    float* o_p    = o_b + BLn;
    float* o_len  = o_p + BLn;
    float* o_loss = o_len + Bn;

    dim3 ggrid(Dn / 128, BLn / 128, 2);   // (8, 256, 2)
    sgemm_qk<<<ggrid, 256>>>(x, Wq, Wk);
    props_kernel<<<BLn, 128>>>(o_p, o_b);
    scan_kernel<<<Bn, 256>>>(o_p, o_b, o_P, o_len);
    gather_kernel<<<BLn, 256>>>(x, o_xd);
    finalize_kernel<<<1, 1>>>(o_loss);
}